// round 7
// baseline (speedup 1.0000x reference)
#include <cuda_runtime.h>
#include <cuda_fp16.h>
#include <cstdint>
#include <cstddef>

#define TT 4
#define BATCH 8
#define NTOK 1024
#define CDIM 768
#define HDIM 3072
#define NHEAD 8
#define DHEAD 96
#define NWIN 128
#define BNALL (BATCH*NTOK)
#define MTOT  (TT*BNALL)
#define QKVC  (3*CDIM)

// ---------------- static scratch ----------------
__device__ __align__(128) float  g_y   [(size_t)MTOT*HDIM];
__device__ __align__(128) __half g_xs0 [(size_t)MTOT*CDIM];
__device__ __align__(128) __half g_xs1 [(size_t)MTOT*CDIM];
__device__ __align__(128) __half g_x1s0[(size_t)MTOT*CDIM];
__device__ __align__(128) __half g_x1s1[(size_t)MTOT*CDIM];
__device__ __align__(128) float  g_x1f [(size_t)MTOT*CDIM];
__device__ __align__(128) __half g_qkvs[(size_t)MTOT*QKVC];
__device__ __align__(128) __half g_osp [(size_t)MTOT*CDIM];
__device__ __align__(128) __half g_hs  [(size_t)MTOT*HDIM];
#define WTOT 7077888
__device__ __align__(128) __half g_w0[WTOT];
__device__ __align__(128) __half g_w1[WTOT];
#define WO_QKV 0
#define WO_P   1769472
#define WO_F1  2359296
#define WO_F2  4718592

// ---------------- helpers ----------------
__device__ __forceinline__ uint32_t s2u(const void* p){
    uint32_t a;
    asm("{ .reg .u64 t; cvta.to.shared.u64 t, %1; cvt.u32.u64 %0, t; }" : "=r"(a) : "l"(p));
    return a;
}
__device__ __forceinline__ void cpasync16(uint32_t s, const void* g){
    asm volatile("cp.async.cg.shared.global [%0], [%1], 16;"
                 :: "r"(s), "l"(__cvta_generic_to_global(g)) : "memory");
}
__device__ __forceinline__ void ldsm4(uint32_t* r, uint32_t a){
    asm volatile("ldmatrix.sync.aligned.m8n8.x4.shared.b16 {%0,%1,%2,%3}, [%4];"
        : "=r"(r[0]),"=r"(r[1]),"=r"(r[2]),"=r"(r[3]) : "r"(a));
}
__device__ __forceinline__ void mma16816(float* c, const uint32_t* a, const uint32_t* b){
    asm volatile("mma.sync.aligned.m16n8k16.row.col.f32.f16.f16.f32 "
        "{%0,%1,%2,%3}, {%4,%5,%6,%7}, {%8,%9}, {%0,%1,%2,%3};"
        : "+f"(c[0]),"+f"(c[1]),"+f"(c[2]),"+f"(c[3])
        : "r"(a[0]),"r"(a[1]),"r"(a[2]),"r"(a[3]), "r"(b[0]),"r"(b[1]));
}

// ---------------- GEMM: Y = (a0+a1)(w0+w1) (float) | s(w0+w1) (spike) ----------------
// Tile 256(M) x 128(N), K-chunk 64; operands loaded once per chunk, multiple passes.
struct GemmP {
    const __half *A0, *A1, *B0, *B1;
    int K; float* Y; int N;
};

template<int SPIKE>
__global__ __launch_bounds__(256) void gemm_mma(GemmP p)
{
    constexpr uint32_t B0OF = SPIKE ? 32768u : 65536u;
    constexpr uint32_t STG  = SPIKE ? 65536u : 98304u;
    constexpr int NP = SPIKE ? 2 : 3;
    constexpr uint32_t AOF[3] = {0u, SPIKE ? 0u : 32768u, 0u};
    constexpr uint32_t BOF[3] = {B0OF, SPIKE ? B0OF + 16384u : B0OF, B0OF + 16384u};

    extern __shared__ char sm[];
    const uint32_t sb = s2u(sm);
    const int tid = threadIdx.x;
    const int m0 = blockIdx.y * 256, n0 = blockIdx.x * 128;
    const int kc = p.K >> 6;

    auto issue = [&](int c){
        const uint32_t stg = sb + (uint32_t)(c & 1) * STG;
        const int k0 = c * 64;
        {   // A0: 256 rows x 128B
            const __half* a0 = p.A0 + (size_t)m0 * p.K + k0;
            #pragma unroll
            for (int i = 0; i < 8; i++){
                const int u = tid + i*256;
                const int row = u >> 3, c16 = u & 7;
                const uint32_t so = (uint32_t)(row*128 + ((c16 ^ (row & 7)) * 16));
                cpasync16(stg + so, a0 + (size_t)row * p.K + c16*8);
            }
        }
        if constexpr (!SPIKE){
            const __half* a1 = p.A1 + (size_t)m0 * p.K + k0;
            #pragma unroll
            for (int i = 0; i < 8; i++){
                const int u = tid + i*256;
                const int row = u >> 3, c16 = u & 7;
                const uint32_t so = (uint32_t)(row*128 + ((c16 ^ (row & 7)) * 16));
                cpasync16(stg + 32768u + so, a1 + (size_t)row * p.K + c16*8);
            }
        }
        {   // B0, B1: 128 rows x 128B each
            const __half* b0 = p.B0 + (size_t)n0 * p.K + k0;
            const __half* b1 = p.B1 + (size_t)n0 * p.K + k0;
            #pragma unroll
            for (int i = 0; i < 4; i++){
                const int u = tid + i*256;
                const int row = u >> 3, c16 = u & 7;
                const uint32_t so = (uint32_t)(row*128 + ((c16 ^ (row & 7)) * 16));
                cpasync16(stg + B0OF + so,          b0 + (size_t)row * p.K + c16*8);
                cpasync16(stg + B0OF + 16384u + so, b1 + (size_t)row * p.K + c16*8);
            }
        }
        asm volatile("cp.async.commit_group;" ::: "memory");
    };

    issue(0); issue(1);

    float acc[4][8][4];
    #pragma unroll
    for (int a=0;a<4;a++)
        #pragma unroll
        for (int b=0;b<8;b++)
            #pragma unroll
            for (int q=0;q<4;q++) acc[a][b][q] = 0.f;

    const int lane = tid & 31, wid = tid >> 5;
    const int wm = wid & 3, wn = wid >> 2;          // 4 x 2 warp grid, 64x64 per warp
    const int arow = (lane & 7) + ((lane >> 3) & 1) * 8;
    const int a_u  = lane >> 4;
    const int brow = (lane & 7) + (lane >> 4) * 8;
    const int b_u  = (lane >> 3) & 1;
    const uint32_t aBO = (uint32_t)((wm*64 + arow) * 128);
    const uint32_t bBO = (uint32_t)((wn*64 + brow) * 128);
    const int aX = arow & 7, bX = brow & 7;

    for (int c = 0; c < kc; c++){
        asm volatile("cp.async.wait_group 1;" ::: "memory");
        __syncthreads();
        const uint32_t stg = sb + (uint32_t)(c & 1) * STG;
        #pragma unroll
        for (int ps = 0; ps < NP; ps++){
            const uint32_t aT = stg + AOF[ps] + aBO;
            const uint32_t bT = stg + BOF[ps] + bBO;
            #pragma unroll
            for (int ks = 0; ks < 4; ks++){
                uint32_t af[4][4], bf[8][2];
                #pragma unroll
                for (int mi = 0; mi < 4; mi++)
                    ldsm4(af[mi], aT + (uint32_t)(mi*2048) +
                          (uint32_t)(((ks*2 + a_u) ^ aX) * 16));
                #pragma unroll
                for (int np = 0; np < 4; np++){
                    uint32_t r[4];
                    ldsm4(r, bT + (uint32_t)(np*2048) +
                          (uint32_t)(((ks*2 + b_u) ^ bX) * 16));
                    bf[2*np][0] = r[0]; bf[2*np][1] = r[1];
                    bf[2*np+1][0] = r[2]; bf[2*np+1][1] = r[3];
                }
                #pragma unroll
                for (int mi = 0; mi < 4; mi++)
                    #pragma unroll
                    for (int ni = 0; ni < 8; ni++)
                        mma16816(acc[mi][ni], af[mi], bf[ni]);
            }
        }
        __syncthreads();
        if (c + 2 < kc) issue(c + 2);
        else asm volatile("cp.async.commit_group;" ::: "memory");
    }

    const int r0 = m0 + wm*64 + (lane >> 2);
    const int c0 = n0 + wn*64 + (lane & 3) * 2;
    #pragma unroll
    for (int mi = 0; mi < 4; mi++){
        #pragma unroll
        for (int ni = 0; ni < 8; ni++){
            float* y = p.Y + (size_t)(r0 + mi*16) * p.N + c0 + ni*8;
            *reinterpret_cast<float2*>(y) = make_float2(acc[mi][ni][0], acc[mi][ni][1]);
            *reinterpret_cast<float2*>(y + (size_t)8 * p.N) =
                make_float2(acc[mi][ni][2], acc[mi][ni][3]);
        }
    }
}

// ---------------- elementwise ----------------
__device__ __forceinline__ void dek2(float a, unsigned short& u0, unsigned short& u1){
    const __half h0 = __float2half_rn(a);
    const float r1 = a - __half2float(h0);
    const __half h1 = __float2half_rn(r1);
    u0 = __half_as_ushort(h0); u1 = __half_as_ushort(h1);
}

__global__ void split2_kernel(const float* __restrict__ src,
                              __half* __restrict__ d0, __half* __restrict__ d1,
                              long long n4)
{
    const long long i = (long long)blockIdx.x * blockDim.x + threadIdx.x;
    if (i >= n4) return;
    const float4 v = *reinterpret_cast<const float4*>(src + i*4);
    unsigned short a0,a1,b0,b1,c0,c1,e0,e1;
    dek2(v.x,a0,a1); dek2(v.y,b0,b1); dek2(v.z,c0,c1); dek2(v.w,e0,e1);
    *reinterpret_cast<uint2*>(d0 + i*4) =
        make_uint2((uint32_t)a0 | ((uint32_t)b0 << 16), (uint32_t)c0 | ((uint32_t)e0 << 16));
    *reinterpret_cast<uint2*>(d1 + i*4) =
        make_uint2((uint32_t)a1 | ((uint32_t)b1 << 16), (uint32_t)c1 | ((uint32_t)e1 << 16));
}

__global__ void lif_plain(const float* __restrict__ Y, const float* __restrict__ Bb,
                          const float* __restrict__ Sc, const float* __restrict__ Sh,
                          __half* __restrict__ O, int OC, int ldY, int ybase,
                          int ldO, int obase)
{
    const long long i = (long long)blockIdx.x * blockDim.x + threadIdx.x;
    if (i >= (long long)BNALL * OC) return;
    const int oc = (int)(i % OC), bn = (int)(i / OC);
    const float b = Bb[oc], s = Sc[oc], h = Sh[oc];
    float v = 0.f;
    #pragma unroll
    for (int t = 0; t < TT; t++){
        const size_t r = (size_t)(t*BNALL + bn);
        const float z = (Y[r*ldY + ybase + oc] + b)*s + h;
        v += (z - v)*0.5f;
        const float sp = (v >= 1.f) ? 1.f : 0.f;
        O[r*ldO + obase + oc] = __float2half(sp);
        v *= (1.f - sp);
    }
}

__global__ void lif_proj(const float* __restrict__ Y, const float* __restrict__ Bb,
                         const float* __restrict__ Sc, const float* __restrict__ Sh,
                         const float* __restrict__ X, float* __restrict__ X1,
                         __half* __restrict__ d0, __half* __restrict__ d1)
{
    const long long i = (long long)blockIdx.x * blockDim.x + threadIdx.x;
    if (i >= (long long)BNALL * CDIM) return;
    const int oc = (int)(i % CDIM), bn = (int)(i / CDIM);
    const float b = Bb[oc], s = Sc[oc], h = Sh[oc];
    float v = 0.f;
    #pragma unroll
    for (int t = 0; t < TT; t++){
        const size_t idx = (size_t)(t*BNALL + bn)*CDIM + oc;
        const float z = (Y[idx] + b)*s + h;
        v += (z - v)*0.5f;
        const float sp = (v >= 1.f) ? 1.f : 0.f;
        const float x1 = X[idx] + sp;
        X1[idx] = x1;
        unsigned short u0,u1; dek2(x1,u0,u1);
        d0[idx] = __ushort_as_half(u0);
        d1[idx] = __ushort_as_half(u1);
        v *= (1.f - sp);
    }
}

__global__ void lif_out(const float* __restrict__ Y, const float* __restrict__ Bb,
                        const float* __restrict__ Sc, const float* __restrict__ Sh,
                        const float* __restrict__ X1, float* __restrict__ Out)
{
    const long long i = (long long)blockIdx.x * blockDim.x + threadIdx.x;
    if (i >= (long long)BNALL * CDIM) return;
    const int oc = (int)(i % CDIM), bn = (int)(i / CDIM);
    const float b = Bb[oc], s = Sc[oc], h = Sh[oc];
    float v = 0.f;
    #pragma unroll
    for (int t = 0; t < TT; t++){
        const size_t idx = (size_t)(t*BNALL + bn)*CDIM + oc;
        const float z = (Y[idx] + b)*s + h;
        v += (z - v)*0.5f;
        const float sp = (v >= 1.f) ? 1.f : 0.f;
        Out[idx] = X1[idx] + sp;
        v *= (1.f - sp);
    }
}

// ---------------- local attention + attn_lif ----------------
__global__ __launch_bounds__(128)
void attn_kernel(const __half* __restrict__ qkv, __half* __restrict__ osp)
{
    const int blk = blockIdx.x;
    const int nw = blk & (NWIN-1);
    const int hh = (blk >> 7) & (NHEAD-1);
    const int bb = blk >> 10;
    const int n0 = nw * 8;
    const int tid = threadIdx.x;

    __shared__ float qs[8][96];
    __shared__ float ks[16][100];
    __shared__ float vs[16][100];
    __shared__ float ps[8][16];
    __shared__ float vst[768];
    for (int idx = tid; idx < 768; idx += 128) vst[idx] = 0.f;

    const int i_ = tid >> 4, j_ = tid & 15;
    const float SCALE = 0.10206207261596577f;

    for (int t = 0; t < TT; t++){
        const int rowbase = (t*BATCH + bb) * NTOK;
        for (int idx = tid; idx < 8*96; idx += 128){
            const int i = idx / 96, d = idx - 96*i;
            qs[i][d] = __half2float(qkv[(size_t)(rowbase + n0 + i)*QKVC + hh*DHEAD + d]);
        }
        for (int idx = tid; idx < 16*96; idx += 128){
            const int j = idx / 96, d = idx - 96*j;
            const int n = n0 - 8 + j;
            float kv = 0.f, vv = 0.f;
            if (n >= 0){
                const size_t base = (size_t)(rowbase + n)*QKVC + hh*DHEAD + d;
                kv = __half2float(qkv[base + CDIM]);
                vv = __half2float(qkv[base + 2*CDIM]);
            }
            ks[j][d] = kv; vs[j][d] = vv;
        }
        __syncthreads();

        float cnt = 0.f;
        {
            const float4* q4 = reinterpret_cast<const float4*>(&qs[i_][0]);
            const float4* k4 = reinterpret_cast<const float4*>(&ks[j_][0]);
            #pragma unroll
            for (int c = 0; c < 24; c++){
                const float4 a = q4[c], b = k4[c];
                cnt += a.x*b.x + a.y*b.y + a.z*b.z + a.w*b.w;
            }
        }
        float sim = cnt * SCALE;
        if (nw == 0 && j_ < 8) sim = -3.402823466e+38f;
        float mx = sim;
        #pragma unroll
        for (int o = 8; o; o >>= 1) mx = fmaxf(mx, __shfl_xor_sync(0xffffffffu, mx, o));
        const float e = expf(sim - mx);
        float smv = e;
        #pragma unroll
        for (int o = 8; o; o >>= 1) smv += __shfl_xor_sync(0xffffffffu, smv, o);
        ps[i_][j_] = e / smv;
        __syncthreads();

        for (int idx = tid; idx < 8*96; idx += 128){
            const int i = idx / 96, d = idx - 96*i;
            float o = 0.f;
            #pragma unroll
            for (int j = 0; j < 16; j++) o += ps[i][j] * vs[j][d];
            float v = vst[idx];
            v += (o - v)*0.5f;
            const float sp = (v >= 0.5f) ? 1.f : 0.f;
            osp[(size_t)(rowbase + n0 + i)*CDIM + hh*DHEAD + d] = __float2half(sp);
            vst[idx] = v * (1.f - sp);
        }
        __syncthreads();
    }
}

// ---------------- launch ----------------
extern "C" void kernel_launch(void* const* d_in, const int* in_sizes, int n_in,
                              void* d_out, int out_size)
{
    const float* x = (const float*)d_in[0];
    const float* W[6]  = {(const float*)d_in[1],(const float*)d_in[5],(const float*)d_in[9],
                          (const float*)d_in[13],(const float*)d_in[17],(const float*)d_in[21]};
    const float* Bb[6] = {(const float*)d_in[2],(const float*)d_in[6],(const float*)d_in[10],
                          (const float*)d_in[14],(const float*)d_in[18],(const float*)d_in[22]};
    const float* Sc[6] = {(const float*)d_in[3],(const float*)d_in[7],(const float*)d_in[11],
                          (const float*)d_in[15],(const float*)d_in[19],(const float*)d_in[23]};
    const float* Sh[6] = {(const float*)d_in[4],(const float*)d_in[8],(const float*)d_in[12],
                          (const float*)d_in[16],(const float*)d_in[20],(const float*)d_in[24]};

    void *py,*pxs0,*pxs1,*px1s0,*px1s1,*px1f,*pqkv,*posp,*phs,*pw0,*pw1;
    cudaGetSymbolAddress(&py, g_y);
    cudaGetSymbolAddress(&pxs0, g_xs0); cudaGetSymbolAddress(&pxs1, g_xs1);
    cudaGetSymbolAddress(&px1s0, g_x1s0); cudaGetSymbolAddress(&px1s1, g_x1s1);
    cudaGetSymbolAddress(&px1f, g_x1f);
    cudaGetSymbolAddress(&pqkv, g_qkvs); cudaGetSymbolAddress(&posp, g_osp);
    cudaGetSymbolAddress(&phs, g_hs);
    cudaGetSymbolAddress(&pw0, g_w0); cudaGetSymbolAddress(&pw1, g_w1);

    __half* w0 = (__half*)pw0;
    __half* w1 = (__half*)pw1;

    cudaFuncSetAttribute(gemm_mma<0>, cudaFuncAttributeMaxDynamicSharedMemorySize, 196608);
    cudaFuncSetAttribute(gemm_mma<1>, cudaFuncAttributeMaxDynamicSharedMemorySize, 131072);

    const struct { int wi; size_t off; long long n; } WS[6] = {
        {0, WO_QKV,           (long long)CDIM*CDIM},
        {1, WO_QKV + 589824,  (long long)CDIM*CDIM},
        {2, WO_QKV + 1179648, (long long)CDIM*CDIM},
        {3, WO_P,             (long long)CDIM*CDIM},
        {4, WO_F1,            (long long)HDIM*CDIM},
        {5, WO_F2,            (long long)CDIM*HDIM}};
    for (int i = 0; i < 6; i++){
        const long long n4 = WS[i].n / 4;
        split2_kernel<<<(int)((n4+255)/256), 256>>>(W[WS[i].wi],
            w0 + WS[i].off, w1 + WS[i].off, n4);
    }
    {
        const long long n4 = (long long)MTOT * CDIM / 4;
        split2_kernel<<<(int)((n4+255)/256), 256>>>(x, (__half*)pxs0, (__half*)pxs1, n4);
    }

    GemmP g;
    // qkv
    g.A0=(__half*)pxs0; g.A1=(__half*)pxs1; g.B0=w0+WO_QKV; g.B1=w1+WO_QKV;
    g.K=CDIM; g.Y=(float*)py; g.N=QKVC;
    gemm_mma<0><<<dim3(QKVC/128, MTOT/256), 256, 196608>>>(g);

    const long long nC = (long long)BNALL*CDIM;
    const int nbC = (int)((nC+255)/256);
    lif_plain<<<nbC,256>>>((float*)py, Bb[0],Sc[0],Sh[0], (__half*)pqkv, CDIM, QKVC, 0,    QKVC, 0);
    lif_plain<<<nbC,256>>>((float*)py, Bb[1],Sc[1],Sh[1], (__half*)pqkv, CDIM, QKVC, 768,  QKVC, 768);
    lif_plain<<<nbC,256>>>((float*)py, Bb[2],Sc[2],Sh[2], (__half*)pqkv, CDIM, QKVC, 1536, QKVC, 1536);

    attn_kernel<<<BATCH*NHEAD*NWIN, 128>>>((const __half*)pqkv, (__half*)posp);

    // proj
    g.A0=(__half*)posp; g.A1=nullptr; g.B0=w0+WO_P; g.B1=w1+WO_P;
    g.K=CDIM; g.Y=(float*)py; g.N=CDIM;
    gemm_mma<1><<<dim3(CDIM/128, MTOT/256), 256, 131072>>>(g);

    lif_proj<<<nbC,256>>>((float*)py, Bb[3],Sc[3],Sh[3], x, (float*)px1f,
                          (__half*)px1s0, (__half*)px1s1);

    // f1
    g.A0=(__half*)px1s0; g.A1=(__half*)px1s1; g.B0=w0+WO_F1; g.B1=w1+WO_F1;
    g.K=CDIM; g.Y=(float*)py; g.N=HDIM;
    gemm_mma<0><<<dim3(HDIM/128, MTOT/256), 256, 196608>>>(g);

    const long long nH = (long long)BNALL*HDIM;
    lif_plain<<<(int)((nH+255)/256),256>>>((float*)py, Bb[4],Sc[4],Sh[4],
                                           (__half*)phs, HDIM, HDIM, 0, HDIM, 0);

    // f2
    g.A0=(__half*)phs; g.A1=nullptr; g.B0=w0+WO_F2; g.B1=w1+WO_F2;
    g.K=HDIM; g.Y=(float*)py; g.N=CDIM;
    gemm_mma<1><<<dim3(CDIM/128, MTOT/256), 256, 131072>>>(g);

    lif_out<<<nbC,256>>>((float*)py, Bb[5],Sc[5],Sh[5], (float*)px1f, (float*)d_out);
}